// round 7
// baseline (speedup 1.0000x reference)
#include <cuda_runtime.h>
#include <cuda_fp16.h>

#define D4 16   // float4s per row (D=64)

static const int NU = 30000, NB = 10000, NI = 60000;

// Concatenated prop node space: UB(40000) | UI(90000) | BI(70000)
#define NPROP 200000
// + agg rows: UIagg(30000) | BIagg(10000)
#define TOT_NODES 240000
#define TOT_EDGES 5600000
#define SCAN_TB 512
#define MAX_BLKS 512

// n_base: 0 | 40000 | 130000 | 200000 | 230000
#define NB_UI 40000
#define NB_BI 130000
#define NB_AGG_U 200000
#define NB_AGG_B 230000

// Static device scratch (allocation-free rule).
__device__ __half g_featA[NPROP * 64];   // 25.6 MB
__device__ __half g_featB[NPROP * 64];   // 25.6 MB
__device__ float  g_acc  [NPROP * 64];   // 51.2 MB  (fp32 accumulators, all 3 props)
__device__ int    g_cnt   [TOT_NODES];
__device__ int    g_rowptr[TOT_NODES + 1];
__device__ int2   g_colval[TOT_EDGES];
__device__ int    g_partials[MAX_BLKS];

struct GraphSet {
    const int*   rows[5];
    const int*   cols[5];
    const float* vals[5];
    int e_base[6];
    int n_base[6];
};
struct PropSrc {
    const float4* a[3];
    const float4* b[3];
    int           na[3];
    const float*  coefs[3];
};

// ---------------------------------------------------------------------------
__global__ void k_zero_int(int* __restrict__ p, int n) {
    int i = blockIdx.x * blockDim.x + threadIdx.x;
    if (i < n) p[i] = 0;
}

__global__ void k_hist_all(GraphSet gs, int tot_e, int* __restrict__ cnt) {
    int i = blockIdx.x * blockDim.x + threadIdx.x;
    if (i >= tot_e) return;
    int g = 0;
    #pragma unroll
    for (int k = 1; k < 5; k++) if (i >= gs.e_base[k]) g = k;
    int ei = i - gs.e_base[g];
    atomicAdd(&cnt[gs.n_base[g] + gs.rows[g][ei]], 1);
}

__global__ void k_partial(const int* __restrict__ cnt, int n, int* __restrict__ partials) {
    __shared__ int s[SCAN_TB];
    int i = blockIdx.x * SCAN_TB + threadIdx.x;
    int t = threadIdx.x;
    s[t] = (i < n) ? cnt[i] : 0;
    __syncthreads();
    for (int o = SCAN_TB / 2; o; o >>= 1) {
        if (t < o) s[t] += s[t + o];
        __syncthreads();
    }
    if (t == 0) partials[blockIdx.x] = s[0];
}

__global__ void k_scan_partials(int* __restrict__ p, int nblk) {
    __shared__ int s[MAX_BLKS];
    int t = threadIdx.x;
    s[t] = (t < nblk) ? p[t] : 0;
    __syncthreads();
    for (int o = 1; o < MAX_BLKS; o <<= 1) {
        int v = (t >= o) ? s[t - o] : 0;
        __syncthreads();
        s[t] += v;
        __syncthreads();
    }
    if (t < nblk) p[t] = (t ? s[t - 1] : 0);
}

__global__ void k_scan_final(int* __restrict__ cnt, int n,
                             const int* __restrict__ partials, int* __restrict__ rowptr) {
    __shared__ int s[SCAN_TB];
    int i = blockIdx.x * SCAN_TB + threadIdx.x;
    int t = threadIdx.x;
    int c = (i < n) ? cnt[i] : 0;
    s[t] = c;
    __syncthreads();
    for (int o = 1; o < SCAN_TB; o <<= 1) {
        int v = (t >= o) ? s[t - o] : 0;
        __syncthreads();
        s[t] += v;
        __syncthreads();
    }
    int start = partials[blockIdx.x] + s[t] - c;
    if (i < n) {
        rowptr[i] = start;
        cnt[i] = start;
        if (i == n - 1) rowptr[n] = start + c;
    }
}

__global__ void k_scatter_all(GraphSet gs, int tot_e,
                              int* __restrict__ pos, int2* __restrict__ colval) {
    int i = blockIdx.x * blockDim.x + threadIdx.x;
    if (i >= tot_e) return;
    int g = 0;
    #pragma unroll
    for (int k = 1; k < 5; k++) if (i >= gs.e_base[k]) g = k;
    int ei = i - gs.e_base[g];
    int p = atomicAdd(&pos[gs.n_base[g] + gs.rows[g][ei]], 1);
    colval[p] = make_int2(gs.cols[g][ei], __float_as_int(gs.vals[g][ei]));
}

// ---------------------------------------------------------------------------
__device__ __forceinline__ float4 ld_half4(const uint2* __restrict__ p, int idx) {
    uint2 u = p[idx];
    __half2 h0 = *reinterpret_cast<__half2*>(&u.x);
    __half2 h1 = *reinterpret_cast<__half2*>(&u.y);
    float2 f0 = __half22float2(h0);
    float2 f1 = __half22float2(h1);
    return make_float4(f0.x, f0.y, f1.x, f1.y);
}

__device__ __forceinline__ uint2 pack_half4(float4 v) {
    __half2 h0 = __floats2half2_rn(v.x, v.y);
    __half2 h1 = __floats2half2_rn(v.z, v.w);
    uint2 u;
    u.x = *reinterpret_cast<unsigned*>(&h0);
    u.y = *reinterpret_cast<unsigned*>(&h1);
    return u;
}

__device__ __forceinline__ void fma4(float4& a, float v, float4 x) {
    a.x += v * x.x; a.y += v * x.y; a.z += v * x.z; a.w += v * x.w;
}

// Merged init for all three props: featA (half) = concat features, acc = c0 * feat (fp32).
__global__ void k_init_all(PropSrc ps, uint2* __restrict__ featA, float4* __restrict__ acc) {
    int i = blockIdx.x * blockDim.x + threadIdx.x;
    if (i >= NPROP * D4) return;
    int row = i >> 4;
    int q   = i & 15;
    int g, lr;
    if (row < NB_UI)       { g = 0; lr = row; }
    else if (row < NB_BI)  { g = 1; lr = row - NB_UI; }
    else                   { g = 2; lr = row - NB_BI; }
    int na = ps.na[g];
    float4 v = (lr < na) ? ps.a[g][lr * D4 + q] : ps.b[g][(lr - na) * D4 + q];
    float c0 = ps.coefs[g][0];
    acc[i] = make_float4(c0 * v.x, c0 * v.y, c0 * v.z, c0 * v.w);
    featA[i] = pack_half4(v);
}

// Merged row-parallel CSR SpMM over all 3 props, fused with l2norm accumulation.
// One warp per row (200k rows); halves take alternating edges; half feat gathers.
__global__ void k_spmm(const int* __restrict__ rowptr, const int2* __restrict__ colval,
                       const uint2* __restrict__ featIn, uint2* __restrict__ featOut,
                       float4* __restrict__ acc_buf, PropSrc ps, int li, int write_out) {
    int w   = (blockIdx.x * blockDim.x + threadIdx.x) >> 5;
    int lid = threadIdx.x & 31;
    if (w >= NPROP) return;
    int half = lid >> 4, q = lid & 15;
    int g     = (w >= NB_BI) ? 2 : ((w >= NB_UI) ? 1 : 0);
    int cbase = (w >= NB_BI) ? NB_BI : ((w >= NB_UI) ? NB_UI : 0);
    int s = rowptr[w], e = rowptr[w + 1];
    float4 a0 = make_float4(0.f, 0.f, 0.f, 0.f);
    float4 a1 = make_float4(0.f, 0.f, 0.f, 0.f);
    int j = s + half;
    for (; j + 6 < e; j += 8) {
        int2 c0 = colval[j], c1 = colval[j + 2], c2 = colval[j + 4], c3 = colval[j + 6];
        float4 x0 = ld_half4(featIn, (cbase + c0.x) * D4 + q);
        float4 x1 = ld_half4(featIn, (cbase + c1.x) * D4 + q);
        float4 x2 = ld_half4(featIn, (cbase + c2.x) * D4 + q);
        float4 x3 = ld_half4(featIn, (cbase + c3.x) * D4 + q);
        fma4(a0, __int_as_float(c0.y), x0);
        fma4(a1, __int_as_float(c1.y), x1);
        fma4(a0, __int_as_float(c2.y), x2);
        fma4(a1, __int_as_float(c3.y), x3);
    }
    for (; j < e; j += 2) {
        int2 cv = colval[j];
        fma4(a0, __int_as_float(cv.y), ld_half4(featIn, (cbase + cv.x) * D4 + q));
    }
    float4 acc = make_float4(a0.x + a1.x, a0.y + a1.y, a0.z + a1.z, a0.w + a1.w);
    acc.x += __shfl_xor_sync(0xffffffffu, acc.x, 16);
    acc.y += __shfl_xor_sync(0xffffffffu, acc.y, 16);
    acc.z += __shfl_xor_sync(0xffffffffu, acc.z, 16);
    acc.w += __shfl_xor_sync(0xffffffffu, acc.w, 16);
    float ss = acc.x * acc.x + acc.y * acc.y + acc.z * acc.z + acc.w * acc.w;
    #pragma unroll
    for (int o = 8; o; o >>= 1) ss += __shfl_xor_sync(0xffffffffu, ss, o);
    float k = ps.coefs[g][li] / fmaxf(sqrtf(ss), 1e-12f);
    if (half == 0) {
        int idx = w * D4 + q;
        if (write_out) featOut[idx] = pack_half4(acc);
        float4 a = acc_buf[idx];
        a.x += k * acc.x; a.y += k * acc.y; a.z += k * acc.z; a.w += k * acc.w;
        acc_buf[idx] = a;
    }
}

// Merged output kernel: users (w<NU) and bundles (w>=NU). fp32 gathers from acc.
__global__ void k_out(const int* __restrict__ rowptr, const int2* __restrict__ colval,
                      const float4* __restrict__ acc, const float* __restrict__ modal,
                      float4* __restrict__ out) {
    int w   = (blockIdx.x * blockDim.x + threadIdx.x) >> 5;
    int lid = threadIdx.x & 31;
    if (w >= NU + NB) return;
    int half = lid >> 4, q = lid & 15;
    bool user = (w < NU);
    int lr    = user ? w : (w - NU);
    int rp    = user ? (NB_AGG_U + w) : (NB_AGG_B + lr);
    int sbase = user ? (NB_BI + NB) : (NB_UI + NU);   // bi items / ui items in acc space
    int s = rowptr[rp], e = rowptr[rp + 1];
    float4 a0 = make_float4(0.f, 0.f, 0.f, 0.f);
    float4 a1 = make_float4(0.f, 0.f, 0.f, 0.f);
    int j = s + half;
    for (; j + 6 < e; j += 8) {
        int2 c0 = colval[j], c1 = colval[j + 2], c2 = colval[j + 4], c3 = colval[j + 6];
        float4 x0 = acc[(sbase + c0.x) * D4 + q];
        float4 x1 = acc[(sbase + c1.x) * D4 + q];
        float4 x2 = acc[(sbase + c2.x) * D4 + q];
        float4 x3 = acc[(sbase + c3.x) * D4 + q];
        fma4(a0, __int_as_float(c0.y), x0);
        fma4(a1, __int_as_float(c1.y), x1);
        fma4(a0, __int_as_float(c2.y), x2);
        fma4(a1, __int_as_float(c3.y), x3);
    }
    for (; j < e; j += 2) {
        int2 cv = colval[j];
        fma4(a0, __int_as_float(cv.y), acc[(sbase + cv.x) * D4 + q]);
    }
    float4 agg = make_float4(a0.x + a1.x, a0.y + a1.y, a0.z + a1.z, a0.w + a1.w);
    agg.x += __shfl_xor_sync(0xffffffffu, agg.x, 16);
    agg.y += __shfl_xor_sync(0xffffffffu, agg.y, 16);
    agg.z += __shfl_xor_sync(0xffffffffu, agg.z, 16);
    agg.w += __shfl_xor_sync(0xffffffffu, agg.w, 16);
    if (half == 0) {
        float m0 = modal[0];
        float mB = user ? modal[1] : modal[2];
        float mC = user ? modal[2] : modal[1];
        int rA = user ? w : (NU + lr);             // ub part (users | bundles)
        int rB = user ? (NB_UI + w) : (NB_BI + lr); // ui_u | bi_b
        float4 u = acc[rA * D4 + q];
        float4 t = acc[rB * D4 + q];
        out[w * D4 + q] =
            make_float4(m0 * u.x + mB * t.x + mC * agg.x,
                        m0 * u.y + mB * t.y + mC * agg.y,
                        m0 * u.z + mB * t.z + mC * agg.z,
                        m0 * u.w + mB * t.w + mC * agg.w);
    }
}

// ---------------------------------------------------------------------------
static inline int ceil_div(int a, int b) { return (a + b - 1) / b; }

extern "C" void kernel_launch(void* const* d_in, const int* in_sizes, int n_in,
                              void* d_out, int out_size) {
    const float* users   = (const float*)d_in[0];
    const float* bundles = (const float*)d_in[1];
    const float* items   = (const float*)d_in[2];
    const int*   ub_rows = (const int*)d_in[3];
    const int*   ub_cols = (const int*)d_in[4];
    const float* ub_vals = (const float*)d_in[5];
    const int*   ui_rows = (const int*)d_in[6];
    const int*   ui_cols = (const int*)d_in[7];
    const float* ui_vals = (const float*)d_in[8];
    const int*   bi_rows = (const int*)d_in[9];
    const int*   bi_cols = (const int*)d_in[10];
    const float* bi_vals = (const float*)d_in[11];
    const int*   bi_agg_rows = (const int*)d_in[12];
    const int*   bi_agg_cols = (const int*)d_in[13];
    const float* bi_agg_vals = (const float*)d_in[14];
    const int*   ui_agg_rows = (const int*)d_in[15];
    const int*   ui_agg_cols = (const int*)d_in[16];
    const float* ui_agg_vals = (const float*)d_in[17];
    const float* ub_coefs  = (const float*)d_in[18];
    const float* ui_coefs  = (const float*)d_in[19];
    const float* bi_coefs  = (const float*)d_in[20];
    const float* modal     = (const float*)d_in[21];

    int nE[5] = { in_sizes[3], in_sizes[6], in_sizes[9], in_sizes[15], in_sizes[12] };
    int nN[5] = { NU + NB, NU + NI, NB + NI, NU, NB };

    __half *featA_h, *featB_h;
    float  *acc_f;
    int *cnt, *rowptr, *partials;
    int2* colval;
    cudaGetSymbolAddress((void**)&featA_h,  g_featA);
    cudaGetSymbolAddress((void**)&featB_h,  g_featB);
    cudaGetSymbolAddress((void**)&acc_f,    g_acc);
    cudaGetSymbolAddress((void**)&cnt,      g_cnt);
    cudaGetSymbolAddress((void**)&rowptr,   g_rowptr);
    cudaGetSymbolAddress((void**)&colval,   g_colval);
    cudaGetSymbolAddress((void**)&partials, g_partials);

    float4* out = (float4*)d_out;
    const int TB = 256;

    GraphSet gs;
    gs.rows[0] = ub_rows;     gs.cols[0] = ub_cols;     gs.vals[0] = ub_vals;
    gs.rows[1] = ui_rows;     gs.cols[1] = ui_cols;     gs.vals[1] = ui_vals;
    gs.rows[2] = bi_rows;     gs.cols[2] = bi_cols;     gs.vals[2] = bi_vals;
    gs.rows[3] = ui_agg_rows; gs.cols[3] = ui_agg_cols; gs.vals[3] = ui_agg_vals;
    gs.rows[4] = bi_agg_rows; gs.cols[4] = bi_agg_cols; gs.vals[4] = bi_agg_vals;
    gs.e_base[0] = 0; gs.n_base[0] = 0;
    for (int g = 0; g < 5; g++) {
        gs.e_base[g + 1] = gs.e_base[g] + nE[g];
        gs.n_base[g + 1] = gs.n_base[g] + nN[g];
    }
    int tot_e = gs.e_base[5];
    int tot_n = gs.n_base[5];
    int nblk = ceil_div(tot_n, SCAN_TB);

    PropSrc ps;
    ps.a[0] = (const float4*)users;   ps.b[0] = (const float4*)bundles; ps.na[0] = NU; ps.coefs[0] = ub_coefs;
    ps.a[1] = (const float4*)users;   ps.b[1] = (const float4*)items;   ps.na[1] = NU; ps.coefs[1] = ui_coefs;
    ps.a[2] = (const float4*)bundles; ps.b[2] = (const float4*)items;   ps.na[2] = NB; ps.coefs[2] = bi_coefs;

    // ---- batched CSR build (all 5 graphs) ----
    k_zero_int<<<ceil_div(tot_n, TB), TB>>>(cnt, tot_n);
    k_hist_all<<<ceil_div(tot_e, TB), TB>>>(gs, tot_e, cnt);
    k_partial<<<nblk, SCAN_TB>>>(cnt, tot_n, partials);
    k_scan_partials<<<1, MAX_BLKS>>>(partials, nblk);
    k_scan_final<<<nblk, SCAN_TB>>>(cnt, tot_n, partials, rowptr);
    k_scatter_all<<<ceil_div(tot_e, TB), TB>>>(gs, tot_e, cnt, colval);

    // ---- merged init (all 3 props) ----
    k_init_all<<<ceil_div(NPROP * D4, TB), TB>>>(ps, (uint2*)featA_h, (float4*)acc_f);

    // ---- merged SpMM layers ----
    int blocks = ceil_div(NPROP * 32, TB);
    k_spmm<<<blocks, TB>>>(rowptr, colval, (const uint2*)featA_h, (uint2*)featB_h,
                           (float4*)acc_f, ps, 1, 1);
    k_spmm<<<blocks, TB>>>(rowptr, colval, (const uint2*)featB_h, (uint2*)featA_h,
                           (float4*)acc_f, ps, 2, 0);

    // ---- merged combine + aggregation output ----
    k_out<<<ceil_div((NU + NB) * 32, TB), TB>>>(rowptr, colval, (const float4*)acc_f, modal, out);
}